// round 15
// baseline (speedup 1.0000x reference)
#include <cuda_runtime.h>
#include <cstdint>

typedef unsigned long long u64;
typedef unsigned int u32;

#define N_BOX   16384
#define POST    1000
#define NMS_TH  0.7f
#define MAX_B   8
#define NW      256            // 64-bit words per full mask row (stride)
#define PRE     1536           // prefix length
#define PNW     (PRE / 64)     // 24 prefix words
#define NZ32    (PRE / 32)     // 48 ballot groups
#define KCAP    1600           // keys capacity
#define MR_TILES 6             // PRE/256
#define SEL_BLKS 8
#define TILE_BLKS (MR_TILES * MR_TILES)     // 36
#define TOT_BLKS (SEL_BLKS + TILE_BLKS)     // 44
#define DYN_SMEM 29696

#define CBASE 0.4117647058823529f     // 0.7/1.7
#define CHI   (CBASE * 1.02f)
#define CLO   (CBASE * 0.98f)

// Global scratch (allocation-free rule -> __device__ globals)
__device__ float4   g_box [MAX_B * N_BOX];
__device__ float    g_area[MAX_B * N_BOX];
__device__ u64      g_mask[(size_t)MAX_B * N_BOX * NW];
__device__ u64      g_diag[MAX_B * N_BOX];
__device__ u64      g_sum [MAX_B * N_BOX * 4];
__device__ int      g_done  [MAX_B];
__device__ int      g_stat  [MAX_B];               // 0 pending, 1 boxes ready, 2 failed
__device__ int      g_cnt_sel [MAX_B];
__device__ int      g_cnt_scat[MAX_B];
__device__ int      g_cnt_sort[MAX_B];
__device__ int      g_cnt_mask[MAX_B];
__device__ u32      g_histpart[MAX_B * SEL_BLKS * 2048];
__device__ u32      g_cursor[MAX_B * 2048];        // zero-init; reset by resolve winner
__device__ u64      g_keys[MAX_B * KCAP];

__device__ __forceinline__ unsigned score_key(float f)
{
    unsigned u   = __float_as_uint(f);
    unsigned asc = u ^ ((u >> 31) ? 0xFFFFFFFFu : 0x80000000u);
    return ~asc;                       // ascending dsc == descending score
}

// monotone-decreasing value-quantized bin: bin 0 = highest scores
__device__ __forceinline__ int score_bin(float f)
{
    float t = (f - 1.0f) * 512.0f;
    int q = (int)floorf(t);
    q = max(0, min(2047, q));
    return 2047 - q;
}

// L2-scoped store of decoded box (cross-block visibility inside one launch)
__device__ __forceinline__ void decode_store_cg(size_t gb, int j, int i,
                                                const float4* anc4, const float4* reg4,
                                                float maxx, float maxy)
{
    float4 A = anc4[i];
    float4 R = reg4[i];
    float cx = A.z * R.x + A.x;
    float cy = A.w * R.y + A.y;
    float w  = A.z * expf(R.z);
    float h  = A.w * expf(R.w);
    float x1 = fminf(fmaxf(cx - w * 0.5f, 0.f), maxx);
    float x2 = fminf(fmaxf(cx + w * 0.5f, 0.f), maxx);
    float y1 = fminf(fmaxf(cy - h * 0.5f, 0.f), maxy);
    float y2 = fminf(fmaxf(cy + h * 0.5f, 0.f), maxy);
    __stcg(&g_box[gb + j], make_float4(x1, y1, x2, y2));
    __stcg(&g_area[gb + j], (x2 - x1) * (y2 - y1));
}

__device__ __forceinline__ u64 shfl_ce(u64 r, int jj, bool up, int lane)
{
    u64 p = __shfl_xor_sync(0xffffffffu, r, jj);
    bool lower   = ((lane & jj) == 0);
    bool takemin = (lower == up);
    return takemin ? (r < p ? r : p) : (r > p ? r : p);
}

__device__ __forceinline__ void spin_ge(int* p, int target)
{
    volatile int* vp = p;
    while (*vp < target) __nanosleep(64);
}

// ------------------------------------------------------------------
// Mega kernel: select (blocks 0..7) + maskgen tiles + resolve (8..43)
// grid (TOT_BLKS, B), 256 threads, DYN_SMEM dynamic shared
// ALL cross-block global traffic uses .cg (L1 is not coherent across SMs)
// ------------------------------------------------------------------
__global__ __launch_bounds__(256, 4)
void mega_kernel(const float* __restrict__ fg,
                 const float* __restrict__ reg,
                 const float* __restrict__ anc,
                 const int*   __restrict__ p_h,
                 const int*   __restrict__ p_w,
                 float* __restrict__ out, int B)
{
    extern __shared__ __align__(16) unsigned char dyn[];
    const int blk  = blockIdx.x;
    const int b    = blockIdx.y;
    const int tid  = threadIdx.x;
    const int lane = tid & 31;
    const int wid  = tid >> 5;
    const size_t gb = (size_t)b * N_BOX;

    // ==================================================================
    // SELECT blocks
    // ==================================================================
    if (blk < SEL_BLKS) {
        u32* hist  = (u32*)dyn;                    // 2048
        u32* sExcl = (u32*)dyn + 2048;             // 2048
        u64* keys  = (u64*)(dyn + 16384);          // KCAP
        __shared__ int s_wsum[8];
        __shared__ int s_T, s_fail, s_win;

        const float4* fgb4 = (const float4*)(fg + gb);

        for (int k = tid; k < 2048; k += 256) hist[k] = 0u;
        if (tid == 0) { s_fail = 0; s_T = 2047; }
        __syncthreads();

        // my 8 elements (kept in registers for the scatter pass)
        float4 fA = fgb4[blk * 512 + tid];
        float4 fB = fgb4[blk * 512 + 256 + tid];
        float fv[8] = { fA.x, fA.y, fA.z, fA.w, fB.x, fB.y, fB.z, fB.w };
        const int jb0 = blk * 2048 + tid * 4;
        const int jb1 = blk * 2048 + 1024 + tid * 4;

        #pragma unroll
        for (int k = 0; k < 8; k++) atomicAdd(&hist[score_bin(fv[k])], 1u);
        __syncthreads();

        // publish partial histogram (L2); barrier #1
        u32* hp = &g_histpart[((size_t)b * SEL_BLKS + blk) * 2048];
        for (int k = tid; k < 2048; k += 256) __stcg(&hp[k], hist[k]);
        __threadfence();
        if (tid == 0) {
            atomicAdd(&g_cnt_sel[b], 1);
            spin_ge(&g_cnt_sel[b], SEL_BLKS);
        }
        __syncthreads();
        __threadfence();

        // reduce 8 partials (L2 loads), identical in all 8 blocks
        {
            const u32* hp0 = &g_histpart[(size_t)b * SEL_BLKS * 2048];
            for (int k = tid; k < 2048; k += 256) {
                unsigned a = 0;
                #pragma unroll
                for (int p = 0; p < SEL_BLKS; p++) a += __ldcg(&hp0[p * 2048 + k]);
                hist[k] = a;
            }
        }
        __syncthreads();

        // scan: thread owns 8 consecutive bins
        const int base = tid * 8;
        unsigned c[8]; int sum = 0;
        #pragma unroll
        for (int k = 0; k < 8; k++) { c[k] = hist[base + k]; sum += (int)c[k]; }
        int incl = sum;
        #pragma unroll
        for (int off = 1; off < 32; off <<= 1) {
            int t = __shfl_up_sync(0xffffffffu, incl, off);
            if (lane >= off) incl += t;
        }
        if (lane == 31) s_wsum[wid] = incl;
        __syncthreads();
        if (tid == 0) {
            int acc = 0;
            #pragma unroll
            for (int i = 0; i < 8; i++) { int t = s_wsum[i]; s_wsum[i] = acc; acc += t; }
        }
        __syncthreads();
        {
            int run = incl - sum + s_wsum[wid];
            #pragma unroll
            for (int k = 0; k < 8; k++) {
                sExcl[base + k] = (unsigned)run;
                if (run < PRE && run + (int)c[k] >= PRE) s_T = base + k;
                run += (int)c[k];
            }
        }
        __syncthreads();
        const int T = s_T;

        // guard: contributing bin >32 -> fail
        #pragma unroll
        for (int k = 0; k < 8; k++)
            if (base + k <= T && c[k] > 32u) s_fail = 1;
        __syncthreads();
        const int M = (int)sExcl[T] + (int)hist[T];
        if (s_fail || M < PRE || M > KCAP) {
            if (blk == 0 && tid == 0) { __threadfence(); atomicExch(&g_stat[b], 2); }
            return;
        }

        // scatter my 8 elements (L2 stores)
        #pragma unroll
        for (int k = 0; k < 8; k++) {
            int bin = score_bin(fv[k]);
            if (bin <= T) {
                unsigned pos = sExcl[bin] + atomicAdd(&g_cursor[b * 2048 + bin], 1u);
                int j = (k < 4) ? (jb0 + k) : (jb1 + k - 4);
                __stcg(&g_keys[b * KCAP + pos],
                       ((u64)score_key(fv[k]) << 32) | (unsigned)j);
            }
        }
        __threadfence();
        if (tid == 0) {
            atomicAdd(&g_cnt_scat[b], 1);
            spin_ge(&g_cnt_scat[b], SEL_BLKS);
        }
        __syncthreads();
        __threadfence();

        // distributed per-bin warp sorts: 64 warps over bins 0..T (L2 ld/st)
        {
            const int gw = blk * 8 + wid;
            for (int bin = gw; bin <= T; bin += SEL_BLKS * 8) {
                const unsigned n = hist[bin];
                if (n == 0u) continue;
                const int s0 = (int)sExcl[bin];
                u64 key = (lane < (int)n) ? __ldcg(&g_keys[b * KCAP + s0 + lane]) : ~0ull;
                #pragma unroll
                for (int k = 2; k <= 32; k <<= 1) {
                    bool up = ((lane & k) == 0);
                    #pragma unroll
                    for (int jj = k >> 1; jj > 0; jj >>= 1)
                        key = shfl_ce(key, jj, up, lane);
                }
                if (lane < (int)n) __stcg(&g_keys[b * KCAP + s0 + lane], key);
            }
        }
        __threadfence();
        if (tid == 0) {
            int old = atomicAdd(&g_cnt_sort[b], 1);
            s_win = (old == SEL_BLKS - 1) ? 1 : 0;
        }
        __syncthreads();
        if (!s_win) return;
        __threadfence();

        // winner: L2-load keys, verify strict ascending, decode top-PRE
        for (int j = tid; j < M; j += 256) keys[j] = __ldcg(&g_keys[b * KCAP + j]);
        __syncthreads();
        for (int j = tid; j < M - 1; j += 256)
            if (keys[j] >= keys[j + 1]) s_fail = 1;
        __syncthreads();
        if (s_fail) {
            if (tid == 0) { __threadfence(); atomicExch(&g_stat[b], 2); }
            return;
        }

        int hv = *p_h, wv = *p_w;
        int H = (hv > 0 && hv < 1000000) ? hv : (int)__int_as_float(hv);
        int W = (wv > 0 && wv < 1000000) ? wv : (int)__int_as_float(wv);
        const float maxy = (float)H - 1.0f;
        const float maxx = (float)W - 1.0f;
        const float4* anc4 = (const float4*)anc + gb;
        const float4* reg4 = (const float4*)reg + gb;
        for (int j = tid; j < PRE; j += 256) {
            int i = (int)(unsigned)(keys[j] & 0xFFFFFFFFull);
            decode_store_cg(gb, j, i, anc4, reg4, maxx, maxy);
        }
        __threadfence();
        __syncthreads();
        if (tid == 0) atomicExch(&g_stat[b], 1);
        return;
    }

    // ==================================================================
    // TILE blocks: wait for boxes, maskgen, last arriver resolves
    // ==================================================================
    const int t  = blk - SEL_BLKS;
    const int rt = t / MR_TILES;
    const int cg = t % MR_TILES;

    __shared__ int s_st, s_win2;
    if (tid == 0) {
        volatile int* vp = &g_stat[b];
        int v;
        while ((v = *vp) == 0) __nanosleep(128);
        s_st = v;
    }
    __syncthreads();
    __threadfence();
    const int st = s_st;

    float4* s_cb = (float4*)dyn;                    // 256
    float2* s_kc = (float2*)(dyn + 4096);           // 256
    float*  s_ca = (float*)(dyn + 6144);            // 256

    if (st == 1 && cg >= rt) {
        const int rowbase = rt << 8;
        const int colbase = cg << 8;
        {
            float4 cb = __ldcg(&g_box [gb + colbase + tid]);
            float  ca = __ldcg(&g_area[gb + colbase + tid]);
            s_cb[tid] = cb;
            s_ca[tid] = ca;
            s_kc[tid] = make_float2(CHI * ca, CLO * ca);
        }
        __syncthreads();

        const int    i   = rowbase + tid;
        const float4 rb  = __ldcg(&g_box [gb + i]);
        const float  ra  = __ldcg(&g_area[gb + i]);
        const float  uhi = CHI * (ra + 1e-9f);
        const float  ulo = CLO * (ra + 1e-9f);
        const int    myw = i >> 6;

        #pragma unroll
        for (int w = 0; w < 4; w++) {
            const int ct = (cg << 2) + w;
            if (ct < myw) continue;

            unsigned acc_h[2], unc_h[2];
            #pragma unroll
            for (int h = 0; h < 2; h++) {
                const int cb0 = (w << 6) + (h << 5);
                unsigned acc = 0, unc = 0;
                #pragma unroll 16
                for (int cc = 31; cc >= 0; cc--) {
                    float4 cb = s_cb[cb0 + cc];
                    float2 kc = s_kc[cb0 + cc];
                    float iw = fminf(rb.z, cb.z) - fmaxf(rb.x, cb.x);
                    float ih = fminf(rb.w, cb.w) - fmaxf(rb.y, cb.y);
                    float inter = fmaxf(iw, 0.f) * fmaxf(ih, 0.f);
                    bool hib = inter > (uhi + kc.x);
                    bool unb = (!hib) && (inter >= (ulo + kc.y));
                    acc = acc * 2u + (hib ? 1u : 0u);
                    unc = unc * 2u + (unb ? 1u : 0u);
                }
                acc_h[h] = acc; unc_h[h] = unc;
            }

            u64 bits  = ((u64)acc_h[1] << 32) | acc_h[0];
            u64 unc64 = ((u64)unc_h[1] << 32) | unc_h[0];

            while (unc64) {                      // rare exact fixup band
                int cc = __ffsll((long long)unc64) - 1; unc64 &= unc64 - 1;
                float4 cb = s_cb[(w << 6) + cc];
                float  ca = s_ca[(w << 6) + cc];
                float iw = fminf(rb.z, cb.z) - fmaxf(rb.x, cb.x);
                float ih = fminf(rb.w, cb.w) - fmaxf(rb.y, cb.y);
                float inter = fmaxf(iw, 0.f) * fmaxf(ih, 0.f);
                float iou = inter / (ra + ca - inter + 1e-9f);
                if (iou > NMS_TH) bits |= 1ull << cc;
            }

            if (ct == myw) {
                int s = (i & 63) + 1;
                u64 m = (s >= 64) ? 0ull : (~0ull << s);
                __stcg(&g_diag[gb + i], bits & m);
            } else if (bits) {
                __stcg(&g_mask[(gb + i) * NW + ct], bits);
                atomicOr(&g_sum[((gb + i) << 2) + (ct >> 6)], 1ull << (ct & 63));
            }
        }
    }

    __threadfence();
    __syncthreads();
    if (tid == 0) {
        int old = atomicAdd(&g_cnt_mask[b], 1);
        s_win2 = (old == TILE_BLKS - 1) ? 1 : 0;
    }
    __syncthreads();
    if (!s_win2) return;
    __threadfence();

    // ---- resolve (winner block) ----
    u64* sdiag = (u64*)dyn;                         // PRE
    u32* ss0   = (u32*)(dyn + PRE * 8);             // PRE
    __shared__ unsigned s_nz32[NZ32];
    __shared__ u64      s_nz [PNW];
    __shared__ u64      remv [PNW];
    __shared__ u64      keepw[PNW];
    __shared__ u64      s_kept;
    __shared__ int      s_cnt;
    __shared__ int      s_scan[32];

    int done = 0;
    if (st == 1) {
        for (int j = tid; j < PRE; j += 256) {
            sdiag[j] = __ldcg(&g_diag[gb + j]);
            ss0[j]   = (unsigned)__ldcg(&g_sum[(gb + j) << 2]);
        }
        if (tid < PNW) { remv[tid] = 0ull; keepw[tid] = 0ull; }
        if (tid == 0)  s_cnt = 0;
        __syncthreads();

        {
            const int w = tid >> 5;                // 8 warps x 192 rows
            #pragma unroll
            for (int k = 0; k < 6; k++) {
                int row = w * 192 + (k << 5) + lane;
                unsigned m = __ballot_sync(0xffffffffu, sdiag[row] != 0ull);
                if (lane == 0) s_nz32[w * 6 + k] = m;
            }
        }
        __syncthreads();
        if (tid < PNW)
            s_nz[tid] = ((u64)s_nz32[2 * tid + 1] << 32) | s_nz32[2 * tid];
        __syncthreads();

        for (int c = 0; c < PNW; c++) {
            if (tid == 0) {
                u64 cur = ~remv[c];
                u64 rem = s_nz[c] & cur;
                const u64* d = &sdiag[c << 6];
                while (rem) {
                    int r = __ffsll((long long)rem) - 1;
                    u64 bit = 1ull << r;
                    rem &= rem - 1;
                    if (cur & bit) {
                        u64 dd = d[r];
                        cur &= ~dd;
                        rem &= ~dd;
                    }
                }
                keepw[c] = cur;
                s_kept   = cur;
                s_cnt   += __popcll(cur);
            }
            __syncthreads();

            const u64 kb = s_kept;
            if (tid < 64 && ((kb >> tid) & 1ull)) {
                const int row = (c << 6) + tid;
                unsigned s = ss0[row] & ~((1u << (c + 1)) - 1u);
                while (s) {
                    int k = __ffs(s) - 1; s &= s - 1;
                    atomicOr(&remv[k], __ldcg(&g_mask[(gb + row) * NW + k]));
                }
            }
            __syncthreads();

            if (s_cnt >= POST) break;
        }
        done = (s_cnt >= POST);

        if (done) {
            float* obox = out;
            float* oidx = out + (size_t)B * POST * 4;
            float* oval = oidx + (size_t)B * POST;

            if (tid < 32) {
                int cnt = (tid < PNW) ? __popcll(keepw[tid]) : 0;
                int scv = cnt;
                #pragma unroll
                for (int off = 1; off < 32; off <<= 1) {
                    int t2 = __shfl_up_sync(0xffffffffu, scv, off);
                    if (tid >= off) scv += t2;
                }
                s_scan[tid] = scv;
            }
            __syncthreads();

            if (tid < PNW) {
                u64 kw = keepw[tid];
                int r = s_scan[tid] - __popcll(kw);
                const int base = tid << 6;
                while (kw && r < POST) {
                    int rr = __ffsll((long long)kw) - 1;
                    kw &= kw - 1;
                    int j = base + rr;
                    float4 bx = __ldcg(&g_box[gb + j]);
                    size_t o = ((size_t)b * POST + r) * 4;
                    obox[o + 0] = bx.x; obox[o + 1] = bx.y;
                    obox[o + 2] = bx.z; obox[o + 3] = bx.w;
                    oidx[(size_t)b * POST + r] = (float)j;
                    oval[(size_t)b * POST + r] = 1.0f;
                    r++;
                }
            }
        }
    }

    // reset all coordination state for next replay (winner only)
    __syncthreads();
    for (int k = tid; k < 2048; k += 256) g_cursor[b * 2048 + k] = 0u;
    if (tid == 0) {
        g_done[b]     = done;
        g_cnt_sel[b]  = 0;
        g_cnt_scat[b] = 0;
        g_cnt_sort[b] = 0;
        g_cnt_mask[b] = 0;
        __threadfence();
        g_stat[b]     = 0;
    }
}

// ------------------------------------------------------------------
// Gated exact fallback — monolith (validated end-to-end in R9/R14)
// ------------------------------------------------------------------
__device__ __forceinline__ void decode_store_fb(size_t gb, int j, int i,
                                                const float4* anc4, const float4* reg4,
                                                float maxx, float maxy)
{
    float4 A = anc4[i];
    float4 R = reg4[i];
    float cx = A.z * R.x + A.x;
    float cy = A.w * R.y + A.y;
    float w  = A.z * expf(R.z);
    float h  = A.w * expf(R.w);
    float x1 = fminf(fmaxf(cx - w * 0.5f, 0.f), maxx);
    float x2 = fminf(fmaxf(cx + w * 0.5f, 0.f), maxx);
    float y1 = fminf(fmaxf(cy - h * 0.5f, 0.f), maxy);
    float y2 = fminf(fmaxf(cy + h * 0.5f, 0.f), maxy);
    g_box [gb + j] = make_float4(x1, y1, x2, y2);
    g_area[gb + j] = (x2 - x1) * (y2 - y1);
}

__global__ __launch_bounds__(1024, 1)
void fallback_kernel(const float* __restrict__ fg,
                     const float* __restrict__ reg,
                     const float* __restrict__ anc,
                     const int*   __restrict__ p_h,
                     const int*   __restrict__ p_w,
                     float* __restrict__ out, int B)
{
    const int b = blockIdx.x;
    if (g_done[b]) return;

    extern __shared__ u64 s_keys[];
    unsigned char* alive = (unsigned char*)s_keys;

    __shared__ int   s_scan[1024];
    __shared__ float s_px1[32], s_py1[32], s_px2[32], s_py2[32], s_pa[32];
    __shared__ int   s_pidx[32], s_cand[32];
    __shared__ int   s_C, s_K, s_cursor, s_last, s_sweepStart;

    const int tid = threadIdx.x;
    const size_t gb = (size_t)b * N_BOX;

    int hv = *p_h, wv = *p_w;
    int H = (hv > 0 && hv < 1000000) ? hv : (int)__int_as_float(hv);
    int W = (wv > 0 && wv < 1000000) ? wv : (int)__int_as_float(wv);
    const float maxy = (float)H - 1.0f;
    const float maxx = (float)W - 1.0f;

    float* obox = out;
    float* oidx = out + (size_t)B * POST * 4;
    float* oval = oidx + (size_t)B * POST;

    const float* fgb = fg + gb;
    for (int j = tid; j < N_BOX; j += 1024)
        s_keys[j] = ((u64)score_key(fgb[j]) << 32) | (unsigned)j;
    for (int r = tid; r < POST; r += 1024) {
        size_t o = ((size_t)b * POST + r) * 4;
        obox[o + 0] = 0.f; obox[o + 1] = 0.f; obox[o + 2] = 0.f; obox[o + 3] = 0.f;
        oidx[(size_t)b * POST + r] = -1.0f;
        oval[(size_t)b * POST + r] = 0.0f;
    }
    __syncthreads();

    for (int k = 2; k <= N_BOX; k <<= 1) {
        for (int jj = k >> 1; jj > 0; jj >>= 1) {
            for (int i = tid; i < N_BOX; i += 1024) {
                int ixj = i ^ jj;
                if (ixj > i) {
                    u64 a = s_keys[i], c = s_keys[ixj];
                    bool up = ((i & k) == 0);
                    if ((a > c) == up) { s_keys[i] = c; s_keys[ixj] = a; }
                }
            }
            __syncthreads();
        }
    }

    const float4* anc4 = (const float4*)anc + gb;
    const float4* reg4 = (const float4*)reg + gb;
    for (int j = tid; j < N_BOX; j += 1024) {
        int i = (int)(unsigned)(s_keys[j] & 0xFFFFFFFFull);
        decode_store_fb(gb, j, i, anc4, reg4, maxx, maxy);
    }
    __syncthreads();

    for (int j = tid; j < N_BOX; j += 1024) alive[j] = 1;
    if (tid == 0) s_cursor = 0;
    __syncthreads();

    for (;;) {
        if (tid < 32) {
            const int lane = tid;
            int cnt = 0, cur = s_cursor;
            while (cnt < 32 && cur < N_BOX) {
                int j = cur + lane;
                bool a = (j < N_BOX) && alive[j];
                unsigned m = __ballot_sync(0xffffffffu, a);
                int avail = __popc(m);
                int r = __popc(m & ((1u << lane) - 1u));
                int need = 32 - cnt;
                if (a && r < need) s_cand[cnt + r] = j;
                if (avail >= need) {
                    if (a && r == need - 1) s_last = j;
                    cnt = 32;
                } else {
                    cnt += avail; cur += 32;
                }
            }
            __syncwarp();
            const int C = cnt;

            float x1 = 0.f, y1 = 0.f, x2 = 0.f, y2 = 0.f, ar = 0.f;
            int ci = -1;
            bool al = (lane < C);
            if (al) {
                ci = s_cand[lane];
                float4 bx = g_box[gb + ci];
                x1 = bx.x; y1 = bx.y; x2 = bx.z; y2 = bx.w;
                ar = g_area[gb + ci];
            }
            for (int p = 0; p < C; p++) {
                unsigned mask = __ballot_sync(0xffffffffu, al);
                if (!((mask >> p) & 1u)) continue;
                float bx1 = __shfl_sync(0xffffffffu, x1, p);
                float by1 = __shfl_sync(0xffffffffu, y1, p);
                float bx2 = __shfl_sync(0xffffffffu, x2, p);
                float by2 = __shfl_sync(0xffffffffu, y2, p);
                float ba  = __shfl_sync(0xffffffffu, ar, p);
                if (al && lane > p) {
                    float iw = fminf(x2, bx2) - fmaxf(x1, bx1);
                    float ih = fminf(y2, by2) - fmaxf(y1, by1);
                    float inter = fmaxf(iw, 0.f) * fmaxf(ih, 0.f);
                    float iou = inter / (ba + ar - inter + 1e-9f);
                    if (iou > NMS_TH) al = false;
                }
            }
            unsigned fm = __ballot_sync(0xffffffffu, al);
            if (lane < C) {
                alive[ci] = al ? (unsigned char)1 : (unsigned char)0;
                if (al) {
                    int r = __popc(fm & ((1u << lane) - 1u));
                    s_px1[r] = x1; s_py1[r] = y1; s_px2[r] = x2; s_py2[r] = y2;
                    s_pa[r]  = ar; s_pidx[r] = ci;
                }
            }
            if (lane == 0) {
                s_K = __popc(fm);
                s_C = C;
                s_sweepStart = (C > 0) ? (s_cand[0] + 1) : N_BOX;
                s_cursor = (C == 32) ? (s_last + 1) : N_BOX;
            }
        }
        __syncthreads();
        if (s_C == 0) break;

        const int K = s_K;
        if (K > 0) {
            for (int j = s_sweepStart + tid; j < N_BOX; j += 1024) {
                if (!alive[j]) continue;
                float4 bx = g_box[gb + j];
                float a = g_area[gb + j];
                for (int p = 0; p < K; p++) {
                    if (s_pidx[p] >= j) break;
                    float iw = fminf(bx.z, s_px2[p]) - fmaxf(bx.x, s_px1[p]);
                    if (iw <= 0.f) continue;
                    float ih = fminf(bx.w, s_py2[p]) - fmaxf(bx.y, s_py1[p]);
                    if (ih <= 0.f) continue;
                    float inter = iw * ih;
                    float iou = inter / (s_pa[p] + a - inter + 1e-9f);
                    if (iou > NMS_TH) { alive[j] = 0; break; }
                }
            }
        }
        __syncthreads();
    }

    const int base = tid * 16;
    int cnt = 0;
    #pragma unroll
    for (int k = 0; k < 16; k++) cnt += alive[base + k];
    int v = cnt;
    s_scan[tid] = v;
    __syncthreads();
    for (int off = 1; off < 1024; off <<= 1) {
        int t = (tid >= off) ? s_scan[tid - off] : 0;
        __syncthreads();
        v += t;
        s_scan[tid] = v;
        __syncthreads();
    }
    int r = v - cnt;
    #pragma unroll
    for (int k = 0; k < 16; k++) {
        int j = base + k;
        if (alive[j]) {
            if (r < POST) {
                float4 bx = g_box[gb + j];
                size_t o = ((size_t)b * POST + r) * 4;
                obox[o + 0] = bx.x; obox[o + 1] = bx.y;
                obox[o + 2] = bx.z; obox[o + 3] = bx.w;
                oidx[(size_t)b * POST + r] = (float)j;
                oval[(size_t)b * POST + r] = 1.0f;
            }
            r++;
        }
    }
}

// ------------------------------------------------------------------
extern "C" void kernel_launch(void* const* d_in, const int* in_sizes, int n_in,
                              void* d_out, int out_size)
{
    const float* fg  = (const float*)d_in[0];
    const float* reg = (const float*)d_in[1];
    const float* anc = (const float*)d_in[2];
    const int*   ph  = (const int*)d_in[3];
    const int*   pw  = (const int*)d_in[4];

    int B = in_sizes[0] / N_BOX;
    if (B < 1) B = 1;
    if (B > MAX_B) B = MAX_B;

    const int FB_SMEM = N_BOX * (int)sizeof(u64);   // 131072
    cudaFuncSetAttribute(fallback_kernel,
                         cudaFuncAttributeMaxDynamicSharedMemorySize, FB_SMEM);

    mega_kernel<<<dim3(TOT_BLKS, B), 256, DYN_SMEM>>>(fg, reg, anc, ph, pw,
                                                      (float*)d_out, B);
    fallback_kernel<<<B, 1024, FB_SMEM>>>(fg, reg, anc, ph, pw, (float*)d_out, B);
}

// round 16
// speedup vs baseline: 267.7176x; 267.7176x over previous
#include <cuda_runtime.h>
#include <cstdint>

typedef unsigned long long u64;

#define N_BOX   16384
#define POST    1000
#define NMS_TH  0.7f
#define MAX_B   8
#define NW      256            // 64-bit words per full mask row (stride)
#define PRE     1536           // prefix length
#define PNW     (PRE / 64)     // 24 prefix words
#define NZ32    (PRE / 32)     // 48 ballot groups
#define KCAP    1600           // keys capacity (M <= 1535+32)
#define MR_TILES 6             // PRE/256

#define CBASE 0.4117647058823529f     // 0.7/1.7
#define CHI   (CBASE * 1.02f)
#define CLO   (CBASE * 0.98f)

// Global scratch (allocation-free rule -> __device__ globals)
__device__ float4   g_box [MAX_B * N_BOX];
__device__ float    g_area[MAX_B * N_BOX];
__device__ u64      g_mask[(size_t)MAX_B * N_BOX * NW];
__device__ u64      g_diag[MAX_B * N_BOX];
__device__ u64      g_sum [MAX_B * N_BOX * 4];
__device__ int      g_done  [MAX_B];     // prefix path produced final output
__device__ int      g_sel_ok[MAX_B];     // top-PRE selection succeeded
__device__ int      g_arrive[MAX_B];     // mask tile arrival counter (reset by select)

__device__ __forceinline__ unsigned score_key(float f)
{
    unsigned u   = __float_as_uint(f);
    unsigned asc = u ^ ((u >> 31) ? 0xFFFFFFFFu : 0x80000000u);
    return ~asc;                       // ascending dsc == descending score
}

// monotone-decreasing value-quantized bin: bin 0 = highest scores
__device__ __forceinline__ int score_bin(float f)
{
    float t = (f - 1.0f) * 512.0f;
    int q = (int)floorf(t);
    q = max(0, min(2047, q));
    return 2047 - q;
}

__device__ __forceinline__ void decode_store(size_t gb, int j, int i,
                                             const float4* anc4, const float4* reg4,
                                             float maxx, float maxy)
{
    float4 A = anc4[i];
    float4 R = reg4[i];
    float cx = A.z * R.x + A.x;
    float cy = A.w * R.y + A.y;
    float w  = A.z * expf(R.z);
    float h  = A.w * expf(R.w);
    float x1 = fminf(fmaxf(cx - w * 0.5f, 0.f), maxx);
    float x2 = fminf(fmaxf(cx + w * 0.5f, 0.f), maxx);
    float y1 = fminf(fmaxf(cy - h * 0.5f, 0.f), maxy);
    float y2 = fminf(fmaxf(cy + h * 0.5f, 0.f), maxy);
    g_box [gb + j] = make_float4(x1, y1, x2, y2);
    g_area[gb + j] = (x2 - x1) * (y2 - y1);
}

__device__ __forceinline__ u64 shfl_ce(u64 r, int jj, bool up, int lane)
{
    u64 p = __shfl_xor_sync(0xffffffffu, r, jj);
    bool lower   = ((lane & jj) == 0);
    bool takemin = (lower == up);
    return takemin ? (r < p ? r : p) : (r > p ? r : p);
}

// ------------------------------------------------------------------
// Kernel A: value-binned top-PRE select + per-bin warp sort + decode
// Histogram uses match_any warp aggregation (bin 2047 holds ~84% of
// elements -> same-address ATOMS would serialize without it).
// ------------------------------------------------------------------
__global__ __launch_bounds__(1024, 1)
void select_kernel(const float* __restrict__ fg,
                   const float* __restrict__ reg,
                   const float* __restrict__ anc,
                   const int*   __restrict__ p_h,
                   const int*   __restrict__ p_w)
{
    __shared__ u64      keys[KCAP];
    __shared__ unsigned hist[2048];
    __shared__ unsigned sPfx[2048];
    __shared__ int      s_wsum[32];
    __shared__ int      s_T, s_fail;

    const int b    = blockIdx.x;
    const int tid  = threadIdx.x;
    const int lane = tid & 31;
    const int wid  = tid >> 5;
    const size_t gb = (size_t)b * N_BOX;
    const float4* fgb4 = (const float4*)(fg + gb);

    hist[tid] = 0u; hist[tid + 1024] = 0u;
    if (tid == 0) { s_fail = 0; s_T = 2047; g_arrive[b] = 0; }   // reset arrival counter
    __syncthreads();

    // load my 16 scores into registers (reused by scatter pass)
    float fv[16];
    #pragma unroll
    for (int k = 0; k < 4; k++) {
        float4 f = fgb4[tid + k * 1024];
        fv[4 * k + 0] = f.x; fv[4 * k + 1] = f.y;
        fv[4 * k + 2] = f.z; fv[4 * k + 3] = f.w;
    }

    // pass 1: histogram with warp aggregation (match_any)
    #pragma unroll
    for (int k = 0; k < 16; k++) {
        int bin = score_bin(fv[k]);
        unsigned mm = __match_any_sync(0xffffffffu, bin);
        int leader = __ffs(mm) - 1;
        if (lane == leader) atomicAdd(&hist[bin], (unsigned)__popc(mm));
    }
    __syncthreads();

    // block scan over bin-pairs (warp shuffles, 2 barriers)
    const unsigned h0 = hist[2 * tid], h1 = hist[2 * tid + 1];
    const int v = (int)(h0 + h1);
    int incl = v;
    #pragma unroll
    for (int off = 1; off < 32; off <<= 1) {
        int t = __shfl_up_sync(0xffffffffu, incl, off);
        if (lane >= off) incl += t;
    }
    if (lane == 31) s_wsum[wid] = incl;
    __syncthreads();
    if (wid == 0) {
        int t = s_wsum[lane];
        int ti = t;
        #pragma unroll
        for (int off = 1; off < 32; off <<= 1) {
            int u = __shfl_up_sync(0xffffffffu, ti, off);
            if (lane >= off) ti += u;
        }
        s_wsum[lane] = ti - t;
    }
    __syncthreads();
    {
        int excl = incl + s_wsum[wid] - v;
        sPfx[2 * tid]     = (unsigned)excl;
        sPfx[2 * tid + 1] = (unsigned)(excl + (int)h0);
        int inc = excl + v;
        if (excl < PRE && inc >= PRE) {
            if (excl + (int)h0 >= PRE) s_T = 2 * tid;
            else                       s_T = 2 * tid + 1;
        }
    }
    __syncthreads();
    const int T = s_T;

    // guard: any contributing bin >32 -> exact fallback
    if ((2 * tid     <= T && h0 > 32u) ||
        (2 * tid + 1 <= T && h1 > 32u)) s_fail = 1;
    __syncthreads();
    if (s_fail) {
        if (tid == 0) g_sel_ok[b] = 0;
        return;
    }

    // pass 2: scatter candidates from registers
    #pragma unroll
    for (int k = 0; k < 16; k++) {
        int bin = score_bin(fv[k]);
        if (bin <= T) {
            unsigned pos = atomicAdd(&sPfx[bin], 1u);
            int j = 4 * (tid + (k >> 2) * 1024) + (k & 3);
            keys[pos] = ((u64)score_key(fv[k]) << 32) | (unsigned)j;
        }
    }
    __syncthreads();

    // per-bin sort: one warp per bin, 32-wide register bitonic on full u64
    for (int bin = wid; bin <= T; bin += 32) {
        const unsigned n = hist[bin];
        if (n == 0u) continue;
        const int s0 = (int)sPfx[bin] - (int)n;
        u64 key = (lane < (int)n) ? keys[s0 + lane] : ~0ull;
        #pragma unroll
        for (int k = 2; k <= 32; k <<= 1) {
            bool up = ((lane & k) == 0);
            #pragma unroll
            for (int jj = k >> 1; jj > 0; jj >>= 1)
                key = shfl_ce(key, jj, up, lane);
        }
        if (lane < (int)n) keys[s0 + lane] = key;
    }
    __syncthreads();

    // end-to-end exactness check: keys unique -> strict ascending required
    const int M = (int)sPfx[T];
    for (int j = tid; j < M - 1; j += 1024)
        if (keys[j] >= keys[j + 1]) s_fail = 1;
    __syncthreads();
    if (s_fail || M < PRE) {
        if (tid == 0) g_sel_ok[b] = 0;
        return;
    }

    // decode top-PRE in exact sorted order
    int hv = *p_h, wv = *p_w;
    int H = (hv > 0 && hv < 1000000) ? hv : (int)__int_as_float(hv);
    int W = (wv > 0 && wv < 1000000) ? wv : (int)__int_as_float(wv);
    const float maxy = (float)H - 1.0f;
    const float maxx = (float)W - 1.0f;
    const float4* anc4 = (const float4*)anc + gb;
    const float4* reg4 = (const float4*)reg + gb;
    for (int j = tid; j < PRE; j += 1024) {
        int i = (int)(unsigned)(keys[j] & 0xFFFFFFFFull);
        decode_store(gb, j, i, anc4, reg4, maxx, maxy);
    }
    if (tid == 0) g_sel_ok[b] = 1;
}

// ------------------------------------------------------------------
// Kernel B: FUSED maskgen + resolve (last-arriving block resolves)
// grid (MR_TILES, MR_TILES, B), 256 threads   [R11 proven]
// ------------------------------------------------------------------
__global__ __launch_bounds__(256, 1)
void mask_resolve_kernel(float* __restrict__ out, int B)
{
    const int b   = blockIdx.z;
    const int rt  = blockIdx.x;
    const int cg  = blockIdx.y;
    const int tid = threadIdx.x;
    const size_t gb = (size_t)b * N_BOX;

    __shared__ float4 s_cb[256];
    __shared__ float2 s_kc[256];
    __shared__ float  s_ca[256];

    const int selok = g_sel_ok[b];

    if (selok && cg >= rt) {
        const int rowbase = rt << 8;
        const int colbase = cg << 8;
        {
            float4 cb = g_box [gb + colbase + tid];
            float  ca = g_area[gb + colbase + tid];
            s_cb[tid] = cb;
            s_ca[tid] = ca;
            s_kc[tid] = make_float2(CHI * ca, CLO * ca);
        }
        __syncthreads();

        const int    i   = rowbase + tid;
        const float4 rb  = g_box [gb + i];
        const float  ra  = g_area[gb + i];
        const float  uhi = CHI * (ra + 1e-9f);
        const float  ulo = CLO * (ra + 1e-9f);
        const int    myw = i >> 6;

        #pragma unroll
        for (int w = 0; w < 4; w++) {
            const int ct = (cg << 2) + w;
            if (ct < myw) continue;

            unsigned acc_h[2], unc_h[2];
            #pragma unroll
            for (int h = 0; h < 2; h++) {
                const int cb0 = (w << 6) + (h << 5);
                unsigned acc = 0, unc = 0;
                #pragma unroll 16
                for (int cc = 31; cc >= 0; cc--) {
                    float4 cb = s_cb[cb0 + cc];
                    float2 kc = s_kc[cb0 + cc];
                    float iw = fminf(rb.z, cb.z) - fmaxf(rb.x, cb.x);
                    float ih = fminf(rb.w, cb.w) - fmaxf(rb.y, cb.y);
                    float inter = fmaxf(iw, 0.f) * fmaxf(ih, 0.f);
                    bool hib = inter > (uhi + kc.x);
                    bool unb = (!hib) && (inter >= (ulo + kc.y));
                    acc = acc * 2u + (hib ? 1u : 0u);
                    unc = unc * 2u + (unb ? 1u : 0u);
                }
                acc_h[h] = acc; unc_h[h] = unc;
            }

            u64 bits  = ((u64)acc_h[1] << 32) | acc_h[0];
            u64 unc64 = ((u64)unc_h[1] << 32) | unc_h[0];

            while (unc64) {                      // rare exact fixup band
                int cc = __ffsll((long long)unc64) - 1; unc64 &= unc64 - 1;
                float4 cb = s_cb[(w << 6) + cc];
                float  ca = s_ca[(w << 6) + cc];
                float iw = fminf(rb.z, cb.z) - fmaxf(rb.x, cb.x);
                float ih = fminf(rb.w, cb.w) - fmaxf(rb.y, cb.y);
                float inter = fmaxf(iw, 0.f) * fmaxf(ih, 0.f);
                float iou = inter / (ra + ca - inter + 1e-9f);
                if (iou > NMS_TH) bits |= 1ull << cc;
            }

            if (ct == myw) {
                int s = (i & 63) + 1;
                u64 m = (s >= 64) ? 0ull : (~0ull << s);
                g_diag[gb + i] = bits & m;
            } else if (bits) {
                g_mask[(gb + i) * NW + ct] = bits;
                atomicOr(&g_sum[((gb + i) << 2) + (ct >> 6)], 1ull << (ct & 63));
            }
        }
    }

    __threadfence();
    __syncthreads();
    __shared__ int s_win;
    if (tid == 0) {
        int old = atomicAdd(&g_arrive[b], 1);
        s_win = (old == MR_TILES * MR_TILES - 1) ? 1 : 0;
    }
    __syncthreads();
    if (!s_win) return;
    __threadfence();

    if (!selok) { if (tid == 0) g_done[b] = 0; return; }

    __shared__ u64      sdiag[PRE];
    __shared__ unsigned ss0  [PRE];
    __shared__ unsigned s_nz32[NZ32];
    __shared__ u64      s_nz [PNW];
    __shared__ u64      remv [PNW];
    __shared__ u64      keepw[PNW];
    __shared__ u64      s_kept;
    __shared__ int      s_cnt;
    __shared__ int      s_scan[32];

    for (int j = tid; j < PRE; j += 256) {
        sdiag[j] = g_diag[gb + j];
        ss0[j]   = (unsigned)g_sum[(gb + j) << 2];
    }
    if (tid < PNW) { remv[tid] = 0ull; keepw[tid] = 0ull; }
    if (tid == 0)  s_cnt = 0;
    __syncthreads();

    {
        const int lane = tid & 31, w = tid >> 5;      // 8 warps x 192 rows
        #pragma unroll
        for (int k = 0; k < 6; k++) {
            int row = w * 192 + (k << 5) + lane;
            unsigned m = __ballot_sync(0xffffffffu, sdiag[row] != 0ull);
            if (lane == 0) s_nz32[w * 6 + k] = m;
        }
    }
    __syncthreads();
    if (tid < PNW)
        s_nz[tid] = ((u64)s_nz32[2 * tid + 1] << 32) | s_nz32[2 * tid];
    __syncthreads();

    for (int c = 0; c < PNW; c++) {
        if (tid == 0) {
            u64 cur = ~remv[c];
            u64 rem = s_nz[c] & cur;
            const u64* d = &sdiag[c << 6];
            while (rem) {
                int r = __ffsll((long long)rem) - 1;
                u64 bit = 1ull << r;
                rem &= rem - 1;
                if (cur & bit) {
                    u64 dd = d[r];
                    cur &= ~dd;
                    rem &= ~dd;
                }
            }
            keepw[c] = cur;
            s_kept   = cur;
            s_cnt   += __popcll(cur);
        }
        __syncthreads();

        const u64 kb = s_kept;
        if (tid < 64 && ((kb >> tid) & 1ull)) {
            const int row = (c << 6) + tid;
            unsigned s = ss0[row] & ~((1u << (c + 1)) - 1u);   // c+1 <= 24 < 32
            while (s) {
                int k = __ffs(s) - 1; s &= s - 1;
                atomicOr(&remv[k], g_mask[(gb + row) * NW + k]);
            }
        }
        __syncthreads();

        if (s_cnt >= POST) break;
    }

    const int done = (s_cnt >= POST);
    if (tid == 0) g_done[b] = done;
    if (!done) return;

    float* obox = out;
    float* oidx = out + (size_t)B * POST * 4;
    float* oval = oidx + (size_t)B * POST;

    if (tid < 32) {
        int cnt = (tid < PNW) ? __popcll(keepw[tid]) : 0;
        int scv = cnt;
        #pragma unroll
        for (int off = 1; off < 32; off <<= 1) {
            int t = __shfl_up_sync(0xffffffffu, scv, off);
            if (tid >= off) scv += t;
        }
        s_scan[tid] = scv;
    }
    __syncthreads();

    if (tid < PNW) {
        u64 kw = keepw[tid];
        int r = s_scan[tid] - __popcll(kw);
        const int base = tid << 6;
        while (kw && r < POST) {
            int rr = __ffsll((long long)kw) - 1;
            kw &= kw - 1;
            int j = base + rr;
            float4 bx = g_box[gb + j];
            size_t o = ((size_t)b * POST + r) * 4;
            obox[o + 0] = bx.x; obox[o + 1] = bx.y;
            obox[o + 2] = bx.z; obox[o + 3] = bx.w;
            oidx[(size_t)b * POST + r] = (float)j;
            oval[(size_t)b * POST + r] = 1.0f;
            r++;
        }
    }
}

// ------------------------------------------------------------------
// Kernel C: gated exact fallback — monolith (validated end-to-end in R9)
// ------------------------------------------------------------------
__global__ __launch_bounds__(1024, 1)
void fallback_kernel(const float* __restrict__ fg,
                     const float* __restrict__ reg,
                     const float* __restrict__ anc,
                     const int*   __restrict__ p_h,
                     const int*   __restrict__ p_w,
                     float* __restrict__ out, int B)
{
    const int b = blockIdx.x;
    if (g_done[b]) return;

    extern __shared__ u64 s_keys[];               // 131072 B; reused as alive[]
    unsigned char* alive = (unsigned char*)s_keys;

    __shared__ int   s_scan[1024];
    __shared__ float s_px1[32], s_py1[32], s_px2[32], s_py2[32], s_pa[32];
    __shared__ int   s_pidx[32], s_cand[32];
    __shared__ int   s_C, s_K, s_cursor, s_last, s_sweepStart;

    const int tid = threadIdx.x;
    const size_t gb = (size_t)b * N_BOX;

    int hv = *p_h, wv = *p_w;
    int H = (hv > 0 && hv < 1000000) ? hv : (int)__int_as_float(hv);
    int W = (wv > 0 && wv < 1000000) ? wv : (int)__int_as_float(wv);
    const float maxy = (float)H - 1.0f;
    const float maxx = (float)W - 1.0f;

    float* obox = out;
    float* oidx = out + (size_t)B * POST * 4;
    float* oval = oidx + (size_t)B * POST;

    const float* fgb = fg + gb;
    for (int j = tid; j < N_BOX; j += 1024)
        s_keys[j] = ((u64)score_key(fgb[j]) << 32) | (unsigned)j;
    for (int r = tid; r < POST; r += 1024) {
        size_t o = ((size_t)b * POST + r) * 4;
        obox[o + 0] = 0.f; obox[o + 1] = 0.f; obox[o + 2] = 0.f; obox[o + 3] = 0.f;
        oidx[(size_t)b * POST + r] = -1.0f;
        oval[(size_t)b * POST + r] = 0.0f;
    }
    __syncthreads();

    for (int k = 2; k <= N_BOX; k <<= 1) {
        for (int jj = k >> 1; jj > 0; jj >>= 1) {
            for (int i = tid; i < N_BOX; i += 1024) {
                int ixj = i ^ jj;
                if (ixj > i) {
                    u64 a = s_keys[i], c = s_keys[ixj];
                    bool up = ((i & k) == 0);
                    if ((a > c) == up) { s_keys[i] = c; s_keys[ixj] = a; }
                }
            }
            __syncthreads();
        }
    }

    const float4* anc4 = (const float4*)anc + gb;
    const float4* reg4 = (const float4*)reg + gb;
    for (int j = tid; j < N_BOX; j += 1024) {
        int i = (int)(unsigned)(s_keys[j] & 0xFFFFFFFFull);
        decode_store(gb, j, i, anc4, reg4, maxx, maxy);
    }
    __syncthreads();

    for (int j = tid; j < N_BOX; j += 1024) alive[j] = 1;
    if (tid == 0) s_cursor = 0;
    __syncthreads();

    for (;;) {
        if (tid < 32) {
            const int lane = tid;
            int cnt = 0, cur = s_cursor;
            while (cnt < 32 && cur < N_BOX) {
                int j = cur + lane;
                bool a = (j < N_BOX) && alive[j];
                unsigned m = __ballot_sync(0xffffffffu, a);
                int avail = __popc(m);
                int r = __popc(m & ((1u << lane) - 1u));
                int need = 32 - cnt;
                if (a && r < need) s_cand[cnt + r] = j;
                if (avail >= need) {
                    if (a && r == need - 1) s_last = j;
                    cnt = 32;
                } else {
                    cnt += avail; cur += 32;
                }
            }
            __syncwarp();
            const int C = cnt;

            float x1 = 0.f, y1 = 0.f, x2 = 0.f, y2 = 0.f, ar = 0.f;
            int ci = -1;
            bool al = (lane < C);
            if (al) {
                ci = s_cand[lane];
                float4 bx = g_box[gb + ci];
                x1 = bx.x; y1 = bx.y; x2 = bx.z; y2 = bx.w;
                ar = g_area[gb + ci];
            }
            for (int p = 0; p < C; p++) {
                unsigned mask = __ballot_sync(0xffffffffu, al);
                if (!((mask >> p) & 1u)) continue;
                float bx1 = __shfl_sync(0xffffffffu, x1, p);
                float by1 = __shfl_sync(0xffffffffu, y1, p);
                float bx2 = __shfl_sync(0xffffffffu, x2, p);
                float by2 = __shfl_sync(0xffffffffu, y2, p);
                float ba  = __shfl_sync(0xffffffffu, ar, p);
                if (al && lane > p) {
                    float iw = fminf(x2, bx2) - fmaxf(x1, bx1);
                    float ih = fminf(y2, by2) - fmaxf(y1, by1);
                    float inter = fmaxf(iw, 0.f) * fmaxf(ih, 0.f);
                    float iou = inter / (ba + ar - inter + 1e-9f);
                    if (iou > NMS_TH) al = false;
                }
            }
            unsigned fm = __ballot_sync(0xffffffffu, al);
            if (lane < C) {
                alive[ci] = al ? (unsigned char)1 : (unsigned char)0;
                if (al) {
                    int r = __popc(fm & ((1u << lane) - 1u));
                    s_px1[r] = x1; s_py1[r] = y1; s_px2[r] = x2; s_py2[r] = y2;
                    s_pa[r]  = ar; s_pidx[r] = ci;
                }
            }
            if (lane == 0) {
                s_K = __popc(fm);
                s_C = C;
                s_sweepStart = (C > 0) ? (s_cand[0] + 1) : N_BOX;
                s_cursor = (C == 32) ? (s_last + 1) : N_BOX;
            }
        }
        __syncthreads();
        if (s_C == 0) break;

        const int K = s_K;
        if (K > 0) {
            for (int j = s_sweepStart + tid; j < N_BOX; j += 1024) {
                if (!alive[j]) continue;
                float4 bx = g_box[gb + j];
                float a = g_area[gb + j];
                for (int p = 0; p < K; p++) {
                    if (s_pidx[p] >= j) break;
                    float iw = fminf(bx.z, s_px2[p]) - fmaxf(bx.x, s_px1[p]);
                    if (iw <= 0.f) continue;
                    float ih = fminf(bx.w, s_py2[p]) - fmaxf(bx.y, s_py1[p]);
                    if (ih <= 0.f) continue;
                    float inter = iw * ih;
                    float iou = inter / (s_pa[p] + a - inter + 1e-9f);
                    if (iou > NMS_TH) { alive[j] = 0; break; }
                }
            }
        }
        __syncthreads();
    }

    const int base = tid * 16;
    int cnt = 0;
    #pragma unroll
    for (int k = 0; k < 16; k++) cnt += alive[base + k];
    int v = cnt;
    s_scan[tid] = v;
    __syncthreads();
    for (int off = 1; off < 1024; off <<= 1) {
        int t = (tid >= off) ? s_scan[tid - off] : 0;
        __syncthreads();
        v += t;
        s_scan[tid] = v;
        __syncthreads();
    }
    int r = v - cnt;
    #pragma unroll
    for (int k = 0; k < 16; k++) {
        int j = base + k;
        if (alive[j]) {
            if (r < POST) {
                float4 bx = g_box[gb + j];
                size_t o = ((size_t)b * POST + r) * 4;
                obox[o + 0] = bx.x; obox[o + 1] = bx.y;
                obox[o + 2] = bx.z; obox[o + 3] = bx.w;
                oidx[(size_t)b * POST + r] = (float)j;
                oval[(size_t)b * POST + r] = 1.0f;
            }
            r++;
        }
    }
}

// ------------------------------------------------------------------
extern "C" void kernel_launch(void* const* d_in, const int* in_sizes, int n_in,
                              void* d_out, int out_size)
{
    const float* fg  = (const float*)d_in[0];
    const float* reg = (const float*)d_in[1];
    const float* anc = (const float*)d_in[2];
    const int*   ph  = (const int*)d_in[3];
    const int*   pw  = (const int*)d_in[4];

    int B = in_sizes[0] / N_BOX;
    if (B < 1) B = 1;
    if (B > MAX_B) B = MAX_B;

    const int FB_SMEM = N_BOX * (int)sizeof(u64);   // 131072
    cudaFuncSetAttribute(fallback_kernel,
                         cudaFuncAttributeMaxDynamicSharedMemorySize, FB_SMEM);

    select_kernel<<<B, 1024>>>(fg, reg, anc, ph, pw);
    mask_resolve_kernel<<<dim3(MR_TILES, MR_TILES, B), 256>>>((float*)d_out, B);
    fallback_kernel<<<B, 1024, FB_SMEM>>>(fg, reg, anc, ph, pw, (float*)d_out, B);
}

// round 17
// speedup vs baseline: 332.9236x; 1.2436x over previous
#include <cuda_runtime.h>
#include <cstdint>

typedef unsigned long long u64;

#define N_BOX   16384
#define POST    1000
#define NMS_TH  0.7f
#define MAX_B   8
#define NW      256            // 64-bit words per full mask row (stride)
#define PRE     1536           // prefix length
#define PNW     (PRE / 64)     // 24 prefix words
#define NZ32    (PRE / 32)     // 48 ballot groups
#define KCAP    1600           // keys capacity (M <= 1535+32)
#define MR_TILES 6             // PRE/256

#define CBASE 0.4117647058823529f     // 0.7/1.7
#define CHI   (CBASE * 1.02f)
#define CLO   (CBASE * 0.98f)

// Global scratch (allocation-free rule -> __device__ globals)
__device__ float4   g_box [MAX_B * N_BOX];
__device__ float    g_area[MAX_B * N_BOX];
__device__ u64      g_mask[(size_t)MAX_B * N_BOX * NW];
__device__ u64      g_diag[MAX_B * N_BOX];
__device__ u64      g_sum [MAX_B * N_BOX * 4];
__device__ int      g_done  [MAX_B];     // prefix path produced final output
__device__ int      g_sel_ok[MAX_B];     // top-PRE selection succeeded
__device__ int      g_arrive[MAX_B];     // mask tile arrival counter (reset by select)

__device__ __forceinline__ unsigned score_key(float f)
{
    unsigned u   = __float_as_uint(f);
    unsigned asc = u ^ ((u >> 31) ? 0xFFFFFFFFu : 0x80000000u);
    return ~asc;                       // ascending dsc == descending score
}

// monotone-decreasing value-quantized bin: bin 0 = highest scores
__device__ __forceinline__ int score_bin(float f)
{
    float t = (f - 1.0f) * 512.0f;
    int q = (int)floorf(t);
    q = max(0, min(2047, q));
    return 2047 - q;
}

__device__ __forceinline__ void decode_store(size_t gb, int j, int i,
                                             const float4* anc4, const float4* reg4,
                                             float maxx, float maxy)
{
    float4 A = anc4[i];
    float4 R = reg4[i];
    float cx = A.z * R.x + A.x;
    float cy = A.w * R.y + A.y;
    float w  = A.z * expf(R.z);
    float h  = A.w * expf(R.w);
    float x1 = fminf(fmaxf(cx - w * 0.5f, 0.f), maxx);
    float x2 = fminf(fmaxf(cx + w * 0.5f, 0.f), maxx);
    float y1 = fminf(fmaxf(cy - h * 0.5f, 0.f), maxy);
    float y2 = fminf(fmaxf(cy + h * 0.5f, 0.f), maxy);
    g_box [gb + j] = make_float4(x1, y1, x2, y2);
    g_area[gb + j] = (x2 - x1) * (y2 - y1);
}

// ------------------------------------------------------------------
// Kernel A: value-binned top-PRE select + per-bin RANK sort + decode
// Per-bin sort: bins are tiny (avg ~1 elem); rank-by-comparison via
// independent smem loads (no 26-cycle dependent SHFL chains).
// ------------------------------------------------------------------
__global__ __launch_bounds__(1024, 1)
void select_kernel(const float* __restrict__ fg,
                   const float* __restrict__ reg,
                   const float* __restrict__ anc,
                   const int*   __restrict__ p_h,
                   const int*   __restrict__ p_w)
{
    __shared__ u64      keys[KCAP];
    __shared__ unsigned hist[2048];
    __shared__ unsigned sPfx[2048];
    __shared__ int      s_wsum[32];
    __shared__ int      s_T, s_fail;

    const int b    = blockIdx.x;
    const int tid  = threadIdx.x;
    const int lane = tid & 31;
    const int wid  = tid >> 5;
    const size_t gb = (size_t)b * N_BOX;
    const float4* fgb4 = (const float4*)(fg + gb);

    hist[tid] = 0u; hist[tid + 1024] = 0u;
    if (tid == 0) { s_fail = 0; s_T = 2047; g_arrive[b] = 0; }   // reset arrival counter
    __syncthreads();

    // load my 16 scores into registers (reused by scatter pass)
    float fv[16];
    #pragma unroll
    for (int k = 0; k < 4; k++) {
        float4 f = fgb4[tid + k * 1024];
        fv[4 * k + 0] = f.x; fv[4 * k + 1] = f.y;
        fv[4 * k + 2] = f.z; fv[4 * k + 3] = f.w;
    }

    // pass 1: histogram with warp aggregation (match_any)
    #pragma unroll
    for (int k = 0; k < 16; k++) {
        int bin = score_bin(fv[k]);
        unsigned mm = __match_any_sync(0xffffffffu, bin);
        int leader = __ffs(mm) - 1;
        if (lane == leader) atomicAdd(&hist[bin], (unsigned)__popc(mm));
    }
    __syncthreads();

    // block scan over bin-pairs (warp shuffles, 2 barriers)
    const unsigned h0 = hist[2 * tid], h1 = hist[2 * tid + 1];
    const int v = (int)(h0 + h1);
    int incl = v;
    #pragma unroll
    for (int off = 1; off < 32; off <<= 1) {
        int t = __shfl_up_sync(0xffffffffu, incl, off);
        if (lane >= off) incl += t;
    }
    if (lane == 31) s_wsum[wid] = incl;
    __syncthreads();
    if (wid == 0) {
        int t = s_wsum[lane];
        int ti = t;
        #pragma unroll
        for (int off = 1; off < 32; off <<= 1) {
            int u = __shfl_up_sync(0xffffffffu, ti, off);
            if (lane >= off) ti += u;
        }
        s_wsum[lane] = ti - t;
    }
    __syncthreads();
    {
        int excl = incl + s_wsum[wid] - v;
        sPfx[2 * tid]     = (unsigned)excl;
        sPfx[2 * tid + 1] = (unsigned)(excl + (int)h0);
        int inc = excl + v;
        if (excl < PRE && inc >= PRE) {
            if (excl + (int)h0 >= PRE) s_T = 2 * tid;
            else                       s_T = 2 * tid + 1;
        }
    }
    __syncthreads();
    const int T = s_T;

    // guard: any contributing bin >32 -> exact fallback
    if ((2 * tid     <= T && h0 > 32u) ||
        (2 * tid + 1 <= T && h1 > 32u)) s_fail = 1;
    __syncthreads();
    if (s_fail) {
        if (tid == 0) g_sel_ok[b] = 0;
        return;
    }

    // pass 2: scatter candidates from registers
    #pragma unroll
    for (int k = 0; k < 16; k++) {
        int bin = score_bin(fv[k]);
        if (bin <= T) {
            unsigned pos = atomicAdd(&sPfx[bin], 1u);
            int j = 4 * (tid + (k >> 2) * 1024) + (k & 3);
            keys[pos] = ((u64)score_key(fv[k]) << 32) | (unsigned)j;
        }
    }
    __syncthreads();

    // per-bin rank sort: one warp per bin; n<=32 guaranteed by guard
    for (int bin = wid; bin <= T; bin += 32) {
        const int n = (int)hist[bin];
        if (n <= 1) continue;                         // singleton: already sorted
        const int s0 = (int)sPfx[bin] - n;            // segment start
        u64 key = 0; int rank = 0;
        if (lane < n) {
            key = keys[s0 + lane];
            for (int p = 0; p < n; p++)               // independent LDS, no dep chain
                rank += (keys[s0 + p] < key) ? 1 : 0;
        }
        __syncwarp();
        if (lane < n) keys[s0 + rank] = key;          // unique keys -> permutation
    }
    __syncthreads();

    // end-to-end exactness check: keys unique -> strict ascending required
    const int M = (int)sPfx[T];
    for (int j = tid; j < M - 1; j += 1024)
        if (keys[j] >= keys[j + 1]) s_fail = 1;
    __syncthreads();
    if (s_fail || M < PRE) {
        if (tid == 0) g_sel_ok[b] = 0;
        return;
    }

    // decode top-PRE in exact sorted order
    int hv = *p_h, wv = *p_w;
    int H = (hv > 0 && hv < 1000000) ? hv : (int)__int_as_float(hv);
    int W = (wv > 0 && wv < 1000000) ? wv : (int)__int_as_float(wv);
    const float maxy = (float)H - 1.0f;
    const float maxx = (float)W - 1.0f;
    const float4* anc4 = (const float4*)anc + gb;
    const float4* reg4 = (const float4*)reg + gb;
    for (int j = tid; j < PRE; j += 1024) {
        int i = (int)(unsigned)(keys[j] & 0xFFFFFFFFull);
        decode_store(gb, j, i, anc4, reg4, maxx, maxy);
    }
    if (tid == 0) g_sel_ok[b] = 1;
}

// ------------------------------------------------------------------
// Kernel B: FUSED maskgen + resolve (last-arriving block resolves)
// grid (MR_TILES, MR_TILES, B), 256 threads   [R11 proven]
// ------------------------------------------------------------------
__global__ __launch_bounds__(256, 1)
void mask_resolve_kernel(float* __restrict__ out, int B)
{
    const int b   = blockIdx.z;
    const int rt  = blockIdx.x;
    const int cg  = blockIdx.y;
    const int tid = threadIdx.x;
    const size_t gb = (size_t)b * N_BOX;

    __shared__ float4 s_cb[256];
    __shared__ float2 s_kc[256];
    __shared__ float  s_ca[256];

    const int selok = g_sel_ok[b];

    if (selok && cg >= rt) {
        const int rowbase = rt << 8;
        const int colbase = cg << 8;
        {
            float4 cb = g_box [gb + colbase + tid];
            float  ca = g_area[gb + colbase + tid];
            s_cb[tid] = cb;
            s_ca[tid] = ca;
            s_kc[tid] = make_float2(CHI * ca, CLO * ca);
        }
        __syncthreads();

        const int    i   = rowbase + tid;
        const float4 rb  = g_box [gb + i];
        const float  ra  = g_area[gb + i];
        const float  uhi = CHI * (ra + 1e-9f);
        const float  ulo = CLO * (ra + 1e-9f);
        const int    myw = i >> 6;

        #pragma unroll
        for (int w = 0; w < 4; w++) {
            const int ct = (cg << 2) + w;
            if (ct < myw) continue;

            unsigned acc_h[2], unc_h[2];
            #pragma unroll
            for (int h = 0; h < 2; h++) {
                const int cb0 = (w << 6) + (h << 5);
                unsigned acc = 0, unc = 0;
                #pragma unroll 16
                for (int cc = 31; cc >= 0; cc--) {
                    float4 cb = s_cb[cb0 + cc];
                    float2 kc = s_kc[cb0 + cc];
                    float iw = fminf(rb.z, cb.z) - fmaxf(rb.x, cb.x);
                    float ih = fminf(rb.w, cb.w) - fmaxf(rb.y, cb.y);
                    float inter = fmaxf(iw, 0.f) * fmaxf(ih, 0.f);
                    bool hib = inter > (uhi + kc.x);
                    bool unb = (!hib) && (inter >= (ulo + kc.y));
                    acc = acc * 2u + (hib ? 1u : 0u);
                    unc = unc * 2u + (unb ? 1u : 0u);
                }
                acc_h[h] = acc; unc_h[h] = unc;
            }

            u64 bits  = ((u64)acc_h[1] << 32) | acc_h[0];
            u64 unc64 = ((u64)unc_h[1] << 32) | unc_h[0];

            while (unc64) {                      // rare exact fixup band
                int cc = __ffsll((long long)unc64) - 1; unc64 &= unc64 - 1;
                float4 cb = s_cb[(w << 6) + cc];
                float  ca = s_ca[(w << 6) + cc];
                float iw = fminf(rb.z, cb.z) - fmaxf(rb.x, cb.x);
                float ih = fminf(rb.w, cb.w) - fmaxf(rb.y, cb.y);
                float inter = fmaxf(iw, 0.f) * fmaxf(ih, 0.f);
                float iou = inter / (ra + ca - inter + 1e-9f);
                if (iou > NMS_TH) bits |= 1ull << cc;
            }

            if (ct == myw) {
                int s = (i & 63) + 1;
                u64 m = (s >= 64) ? 0ull : (~0ull << s);
                g_diag[gb + i] = bits & m;
            } else if (bits) {
                g_mask[(gb + i) * NW + ct] = bits;
                atomicOr(&g_sum[((gb + i) << 2) + (ct >> 6)], 1ull << (ct & 63));
            }
        }
    }

    __threadfence();
    __syncthreads();
    __shared__ int s_win;
    if (tid == 0) {
        int old = atomicAdd(&g_arrive[b], 1);
        s_win = (old == MR_TILES * MR_TILES - 1) ? 1 : 0;
    }
    __syncthreads();
    if (!s_win) return;
    __threadfence();

    if (!selok) { if (tid == 0) g_done[b] = 0; return; }

    __shared__ u64      sdiag[PRE];
    __shared__ unsigned ss0  [PRE];
    __shared__ unsigned s_nz32[NZ32];
    __shared__ u64      s_nz [PNW];
    __shared__ u64      remv [PNW];
    __shared__ u64      keepw[PNW];
    __shared__ u64      s_kept;
    __shared__ int      s_cnt;
    __shared__ int      s_scan[32];

    for (int j = tid; j < PRE; j += 256) {
        sdiag[j] = g_diag[gb + j];
        ss0[j]   = (unsigned)g_sum[(gb + j) << 2];
    }
    if (tid < PNW) { remv[tid] = 0ull; keepw[tid] = 0ull; }
    if (tid == 0)  s_cnt = 0;
    __syncthreads();

    {
        const int lane = tid & 31, w = tid >> 5;      // 8 warps x 192 rows
        #pragma unroll
        for (int k = 0; k < 6; k++) {
            int row = w * 192 + (k << 5) + lane;
            unsigned m = __ballot_sync(0xffffffffu, sdiag[row] != 0ull);
            if (lane == 0) s_nz32[w * 6 + k] = m;
        }
    }
    __syncthreads();
    if (tid < PNW)
        s_nz[tid] = ((u64)s_nz32[2 * tid + 1] << 32) | s_nz32[2 * tid];
    __syncthreads();

    for (int c = 0; c < PNW; c++) {
        if (tid == 0) {
            u64 cur = ~remv[c];
            u64 rem = s_nz[c] & cur;
            const u64* d = &sdiag[c << 6];
            while (rem) {
                int r = __ffsll((long long)rem) - 1;
                u64 bit = 1ull << r;
                rem &= rem - 1;
                if (cur & bit) {
                    u64 dd = d[r];
                    cur &= ~dd;
                    rem &= ~dd;
                }
            }
            keepw[c] = cur;
            s_kept   = cur;
            s_cnt   += __popcll(cur);
        }
        __syncthreads();

        const u64 kb = s_kept;
        if (tid < 64 && ((kb >> tid) & 1ull)) {
            const int row = (c << 6) + tid;
            unsigned s = ss0[row] & ~((1u << (c + 1)) - 1u);   // c+1 <= 24 < 32
            while (s) {
                int k = __ffs(s) - 1; s &= s - 1;
                atomicOr(&remv[k], g_mask[(gb + row) * NW + k]);
            }
        }
        __syncthreads();

        if (s_cnt >= POST) break;
    }

    const int done = (s_cnt >= POST);
    if (tid == 0) g_done[b] = done;
    if (!done) return;

    float* obox = out;
    float* oidx = out + (size_t)B * POST * 4;
    float* oval = oidx + (size_t)B * POST;

    if (tid < 32) {
        int cnt = (tid < PNW) ? __popcll(keepw[tid]) : 0;
        int scv = cnt;
        #pragma unroll
        for (int off = 1; off < 32; off <<= 1) {
            int t = __shfl_up_sync(0xffffffffu, scv, off);
            if (tid >= off) scv += t;
        }
        s_scan[tid] = scv;
    }
    __syncthreads();

    if (tid < PNW) {
        u64 kw = keepw[tid];
        int r = s_scan[tid] - __popcll(kw);
        const int base = tid << 6;
        while (kw && r < POST) {
            int rr = __ffsll((long long)kw) - 1;
            kw &= kw - 1;
            int j = base + rr;
            float4 bx = g_box[gb + j];
            size_t o = ((size_t)b * POST + r) * 4;
            obox[o + 0] = bx.x; obox[o + 1] = bx.y;
            obox[o + 2] = bx.z; obox[o + 3] = bx.w;
            oidx[(size_t)b * POST + r] = (float)j;
            oval[(size_t)b * POST + r] = 1.0f;
            r++;
        }
    }
}

// ------------------------------------------------------------------
// Kernel C: gated exact fallback — monolith (validated end-to-end in R9)
// ------------------------------------------------------------------
__global__ __launch_bounds__(1024, 1)
void fallback_kernel(const float* __restrict__ fg,
                     const float* __restrict__ reg,
                     const float* __restrict__ anc,
                     const int*   __restrict__ p_h,
                     const int*   __restrict__ p_w,
                     float* __restrict__ out, int B)
{
    const int b = blockIdx.x;
    if (g_done[b]) return;

    extern __shared__ u64 s_keys[];               // 131072 B; reused as alive[]
    unsigned char* alive = (unsigned char*)s_keys;

    __shared__ int   s_scan[1024];
    __shared__ float s_px1[32], s_py1[32], s_px2[32], s_py2[32], s_pa[32];
    __shared__ int   s_pidx[32], s_cand[32];
    __shared__ int   s_C, s_K, s_cursor, s_last, s_sweepStart;

    const int tid = threadIdx.x;
    const size_t gb = (size_t)b * N_BOX;

    int hv = *p_h, wv = *p_w;
    int H = (hv > 0 && hv < 1000000) ? hv : (int)__int_as_float(hv);
    int W = (wv > 0 && wv < 1000000) ? wv : (int)__int_as_float(wv);
    const float maxy = (float)H - 1.0f;
    const float maxx = (float)W - 1.0f;

    float* obox = out;
    float* oidx = out + (size_t)B * POST * 4;
    float* oval = oidx + (size_t)B * POST;

    const float* fgb = fg + gb;
    for (int j = tid; j < N_BOX; j += 1024)
        s_keys[j] = ((u64)score_key(fgb[j]) << 32) | (unsigned)j;
    for (int r = tid; r < POST; r += 1024) {
        size_t o = ((size_t)b * POST + r) * 4;
        obox[o + 0] = 0.f; obox[o + 1] = 0.f; obox[o + 2] = 0.f; obox[o + 3] = 0.f;
        oidx[(size_t)b * POST + r] = -1.0f;
        oval[(size_t)b * POST + r] = 0.0f;
    }
    __syncthreads();

    for (int k = 2; k <= N_BOX; k <<= 1) {
        for (int jj = k >> 1; jj > 0; jj >>= 1) {
            for (int i = tid; i < N_BOX; i += 1024) {
                int ixj = i ^ jj;
                if (ixj > i) {
                    u64 a = s_keys[i], c = s_keys[ixj];
                    bool up = ((i & k) == 0);
                    if ((a > c) == up) { s_keys[i] = c; s_keys[ixj] = a; }
                }
            }
            __syncthreads();
        }
    }

    const float4* anc4 = (const float4*)anc + gb;
    const float4* reg4 = (const float4*)reg + gb;
    for (int j = tid; j < N_BOX; j += 1024) {
        int i = (int)(unsigned)(s_keys[j] & 0xFFFFFFFFull);
        decode_store(gb, j, i, anc4, reg4, maxx, maxy);
    }
    __syncthreads();

    for (int j = tid; j < N_BOX; j += 1024) alive[j] = 1;
    if (tid == 0) s_cursor = 0;
    __syncthreads();

    for (;;) {
        if (tid < 32) {
            const int lane = tid;
            int cnt = 0, cur = s_cursor;
            while (cnt < 32 && cur < N_BOX) {
                int j = cur + lane;
                bool a = (j < N_BOX) && alive[j];
                unsigned m = __ballot_sync(0xffffffffu, a);
                int avail = __popc(m);
                int r = __popc(m & ((1u << lane) - 1u));
                int need = 32 - cnt;
                if (a && r < need) s_cand[cnt + r] = j;
                if (avail >= need) {
                    if (a && r == need - 1) s_last = j;
                    cnt = 32;
                } else {
                    cnt += avail; cur += 32;
                }
            }
            __syncwarp();
            const int C = cnt;

            float x1 = 0.f, y1 = 0.f, x2 = 0.f, y2 = 0.f, ar = 0.f;
            int ci = -1;
            bool al = (lane < C);
            if (al) {
                ci = s_cand[lane];
                float4 bx = g_box[gb + ci];
                x1 = bx.x; y1 = bx.y; x2 = bx.z; y2 = bx.w;
                ar = g_area[gb + ci];
            }
            for (int p = 0; p < C; p++) {
                unsigned mask = __ballot_sync(0xffffffffu, al);
                if (!((mask >> p) & 1u)) continue;
                float bx1 = __shfl_sync(0xffffffffu, x1, p);
                float by1 = __shfl_sync(0xffffffffu, y1, p);
                float bx2 = __shfl_sync(0xffffffffu, x2, p);
                float by2 = __shfl_sync(0xffffffffu, y2, p);
                float ba  = __shfl_sync(0xffffffffu, ar, p);
                if (al && lane > p) {
                    float iw = fminf(x2, bx2) - fmaxf(x1, bx1);
                    float ih = fminf(y2, by2) - fmaxf(y1, by1);
                    float inter = fmaxf(iw, 0.f) * fmaxf(ih, 0.f);
                    float iou = inter / (ba + ar - inter + 1e-9f);
                    if (iou > NMS_TH) al = false;
                }
            }
            unsigned fm = __ballot_sync(0xffffffffu, al);
            if (lane < C) {
                alive[ci] = al ? (unsigned char)1 : (unsigned char)0;
                if (al) {
                    int r = __popc(fm & ((1u << lane) - 1u));
                    s_px1[r] = x1; s_py1[r] = y1; s_px2[r] = x2; s_py2[r] = y2;
                    s_pa[r]  = ar; s_pidx[r] = ci;
                }
            }
            if (lane == 0) {
                s_K = __popc(fm);
                s_C = C;
                s_sweepStart = (C > 0) ? (s_cand[0] + 1) : N_BOX;
                s_cursor = (C == 32) ? (s_last + 1) : N_BOX;
            }
        }
        __syncthreads();
        if (s_C == 0) break;

        const int K = s_K;
        if (K > 0) {
            for (int j = s_sweepStart + tid; j < N_BOX; j += 1024) {
                if (!alive[j]) continue;
                float4 bx = g_box[gb + j];
                float a = g_area[gb + j];
                for (int p = 0; p < K; p++) {
                    if (s_pidx[p] >= j) break;
                    float iw = fminf(bx.z, s_px2[p]) - fmaxf(bx.x, s_px1[p]);
                    if (iw <= 0.f) continue;
                    float ih = fminf(bx.w, s_py2[p]) - fmaxf(bx.y, s_py1[p]);
                    if (ih <= 0.f) continue;
                    float inter = iw * ih;
                    float iou = inter / (s_pa[p] + a - inter + 1e-9f);
                    if (iou > NMS_TH) { alive[j] = 0; break; }
                }
            }
        }
        __syncthreads();
    }

    const int base = tid * 16;
    int cnt = 0;
    #pragma unroll
    for (int k = 0; k < 16; k++) cnt += alive[base + k];
    int v = cnt;
    s_scan[tid] = v;
    __syncthreads();
    for (int off = 1; off < 1024; off <<= 1) {
        int t = (tid >= off) ? s_scan[tid - off] : 0;
        __syncthreads();
        v += t;
        s_scan[tid] = v;
        __syncthreads();
    }
    int r = v - cnt;
    #pragma unroll
    for (int k = 0; k < 16; k++) {
        int j = base + k;
        if (alive[j]) {
            if (r < POST) {
                float4 bx = g_box[gb + j];
                size_t o = ((size_t)b * POST + r) * 4;
                obox[o + 0] = bx.x; obox[o + 1] = bx.y;
                obox[o + 2] = bx.z; obox[o + 3] = bx.w;
                oidx[(size_t)b * POST + r] = (float)j;
                oval[(size_t)b * POST + r] = 1.0f;
            }
            r++;
        }
    }
}

// ------------------------------------------------------------------
extern "C" void kernel_launch(void* const* d_in, const int* in_sizes, int n_in,
                              void* d_out, int out_size)
{
    const float* fg  = (const float*)d_in[0];
    const float* reg = (const float*)d_in[1];
    const float* anc = (const float*)d_in[2];
    const int*   ph  = (const int*)d_in[3];
    const int*   pw  = (const int*)d_in[4];

    int B = in_sizes[0] / N_BOX;
    if (B < 1) B = 1;
    if (B > MAX_B) B = MAX_B;

    const int FB_SMEM = N_BOX * (int)sizeof(u64);   // 131072
    cudaFuncSetAttribute(fallback_kernel,
                         cudaFuncAttributeMaxDynamicSharedMemorySize, FB_SMEM);

    select_kernel<<<B, 1024>>>(fg, reg, anc, ph, pw);
    mask_resolve_kernel<<<dim3(MR_TILES, MR_TILES, B), 256>>>((float*)d_out, B);
    fallback_kernel<<<B, 1024, FB_SMEM>>>(fg, reg, anc, ph, pw, (float*)d_out, B);
}